// round 2
// baseline (speedup 1.0000x reference)
#include <cuda_runtime.h>
#include <math.h>

#define B_   64
#define Q_   512
#define KK_  512
#define C_   256
#define H_   8
#define HD_  32
#define OUT_ 256
#define SCALE_Q 0.17677669529663687f   // 1/sqrt(32)

// ---------------- scratch (static device globals; no allocation) -------------
__device__ float g_q[B_ * Q_ * C_];      // scaled q projection  [b,q,h*32+d]
__device__ float g_gate[B_ * Q_ * C_];   // sigmoid gate         [b,q,h*32+d]
__device__ float g_k[B_ * KK_ * C_];     // k projection         [b,k,h*32+d]
__device__ float g_v[B_ * KK_ * C_];     // v projection         [b,k,h*32+d]
__device__ float g_wa[B_ * Q_ * C_];     // gated weighted avg   [b,q,h*32+d]

// ---------------- projection / output GEMM ----------------------------------
// C[M,Ncat] = A[M,256] * W[256,Ncat], 64x64 tile, BK=32, 256 threads, 4x4/thread
// MODE 0: A=q_data, W0=query_w (cols 0..255 -> g_q * SCALE),
//                    W1=gating_w (cols 256..511 -> sigmoid(.+gating_b) -> g_gate)
// MODE 1: A=m_data, W0=key_w -> g_k, W1=value_w -> g_v
// MODE 2: A=g_wa,   W0=output_w, +output_b -> Dout
template <int MODE>
__global__ void __launch_bounds__(256) proj_kernel(const float* __restrict__ A,
                                                   const float* __restrict__ W0,
                                                   const float* __restrict__ W1,
                                                   const float* __restrict__ bvec,
                                                   float* __restrict__ Dout) {
    __shared__ float As[64][36];   // [BM][BK+pad], 16B-aligned rows
    __shared__ float Bs[32][64];   // [BK][BN]

    const int tid = threadIdx.x;
    const int m0  = blockIdx.x * 64;
    const int bn  = blockIdx.y;

    const float* Ap = (MODE == 2) ? g_wa : A;
    const float* W  = (MODE == 2) ? W0 : (bn < 4 ? W0 : W1);
    const int ncol  = (MODE == 2) ? bn * 64 : (bn & 3) * 64;

    const int ty = tid >> 4;   // 0..15 -> row group
    const int tx = tid & 15;   // 0..15 -> col group

    float acc[4][4] = {};

    for (int k0 = 0; k0 < 256; k0 += 32) {
        // load A tile 64x32 (512 float4, 2/thread), row-major into As[row][col]
#pragma unroll
        for (int i = 0; i < 2; i++) {
            int v  = i * 256 + tid;
            int r  = v >> 3;
            int c4 = (v & 7) * 4;
            *(float4*)&As[r][c4] =
                *(const float4*)(Ap + (size_t)(m0 + r) * 256 + k0 + c4);
        }
        // load W tile 32x64
#pragma unroll
        for (int i = 0; i < 2; i++) {
            int v  = i * 256 + tid;
            int r  = v >> 4;
            int c4 = (v & 15) * 4;
            *(float4*)&Bs[r][c4] =
                *(const float4*)(W + (size_t)(k0 + r) * 256 + ncol + c4);
        }
        __syncthreads();

#pragma unroll
        for (int kk = 0; kk < 32; kk++) {
            float ar[4], br[4];
#pragma unroll
            for (int i = 0; i < 4; i++) ar[i] = As[ty * 4 + i][kk];
            float4 b4 = *(const float4*)&Bs[kk][tx * 4];
            br[0] = b4.x; br[1] = b4.y; br[2] = b4.z; br[3] = b4.w;
#pragma unroll
            for (int i = 0; i < 4; i++)
#pragma unroll
                for (int j = 0; j < 4; j++) acc[i][j] += ar[i] * br[j];
        }
        __syncthreads();
    }

#pragma unroll
    for (int i = 0; i < 4; i++) {
        const int row = m0 + ty * 4 + i;
#pragma unroll
        for (int j = 0; j < 4; j++) {
            const int col = ncol + tx * 4 + j;
            const float v = acc[i][j];
            if (MODE == 0) {
                if (bn < 4)
                    g_q[(size_t)row * 256 + col] = v * SCALE_Q;
                else
                    g_gate[(size_t)row * 256 + col] =
                        1.0f / (1.0f + __expf(-(v + bvec[col])));
            } else if (MODE == 1) {
                if (bn < 4)
                    g_k[(size_t)row * 256 + col] = v;
                else
                    g_v[(size_t)row * 256 + col] = v;
            } else {
                Dout[(size_t)row * 256 + col] = v + bvec[col];
            }
        }
    }
}

// ---------------- fused attention (S + bias + softmax + PV + gate) -----------
// grid: (Q/16, H, B), 256 threads. Full 16x512 logits tile in smem.
__global__ void __launch_bounds__(256) attn_kernel(const float* __restrict__ bias,
                                                   const float* __restrict__ nbb) {
    __shared__ float qs[16][36];
    __shared__ float ss[16][512];
    __shared__ float cs[64][36];

    const int tid = threadIdx.x;
    const int q0  = blockIdx.x * 16;
    const int h   = blockIdx.y;
    const int b   = blockIdx.z;

    const float* qbase = g_q + ((size_t)(b * Q_ + q0) * C_ + h * HD_);
    const float* kbase = g_k + ((size_t)b * KK_ * C_ + h * HD_);
    const float* vbase = g_v + ((size_t)b * KK_ * C_ + h * HD_);
    const float* bb    = bias + ((size_t)b * Q_ + q0) * KK_;
    const float* nb    = nbb + ((size_t)h * Q_ + q0) * KK_;

    // load q tile: 16 rows x 32 dims = 128 float4
    if (tid < 128) {
        int r  = tid >> 3;
        int d4 = (tid & 7) * 4;
        *(float4*)&qs[r][d4] = *(const float4*)(qbase + (size_t)r * C_ + d4);
    }
    __syncthreads();

    const int qi  = tid >> 4;        // 0..15
    const int kj0 = (tid & 15) * 4;  // 0..60

    float qreg[32];
#pragma unroll
    for (int d = 0; d < 32; d++) qreg[d] = qs[qi][d];

    // ---- S = q k^T + bias + nonbatched_bias ----
    for (int kc = 0; kc < 8; kc++) {
        __syncthreads();   // previous chunk fully consumed
#pragma unroll
        for (int i = 0; i < 2; i++) {
            int v  = i * 256 + tid;
            int r  = v >> 3;
            int d4 = (v & 7) * 4;
            *(float4*)&cs[r][d4] =
                *(const float4*)(kbase + (size_t)(kc * 64 + r) * C_ + d4);
        }
        __syncthreads();

        float4 bi = *(const float4*)(bb + (size_t)qi * KK_ + kc * 64 + kj0);
        float4 ni = *(const float4*)(nb + (size_t)qi * KK_ + kc * 64 + kj0);
        float badd[4] = {bi.x + ni.x, bi.y + ni.y, bi.z + ni.z, bi.w + ni.w};

#pragma unroll
        for (int j = 0; j < 4; j++) {
            const float4* crow = (const float4*)&cs[kj0 + j][0];
            float dot = 0.0f;
#pragma unroll
            for (int d4 = 0; d4 < 8; d4++) {
                float4 c = crow[d4];
                dot += qreg[d4 * 4 + 0] * c.x + qreg[d4 * 4 + 1] * c.y +
                       qreg[d4 * 4 + 2] * c.z + qreg[d4 * 4 + 3] * c.w;
            }
            ss[qi][kc * 64 + kj0 + j] = dot + badd[j];
        }
    }
    __syncthreads();

    // ---- softmax over k (8 warps x 2 rows) ----
    const int warp = tid >> 5, lane = tid & 31;
#pragma unroll
    for (int rr = 0; rr < 2; rr++) {
        const int r = warp * 2 + rr;
        float mx = -1e30f;
        for (int k = lane; k < 512; k += 32) mx = fmaxf(mx, ss[r][k]);
#pragma unroll
        for (int o = 16; o > 0; o >>= 1)
            mx = fmaxf(mx, __shfl_xor_sync(0xffffffff, mx, o));
        float sum = 0.0f;
        for (int k = lane; k < 512; k += 32) {
            float e = __expf(ss[r][k] - mx);
            ss[r][k] = e;
            sum += e;
        }
#pragma unroll
        for (int o = 16; o > 0; o >>= 1)
            sum += __shfl_xor_sync(0xffffffff, sum, o);
        const float inv = 1.0f / sum;
        for (int k = lane; k < 512; k += 32) ss[r][k] *= inv;
    }
    __syncthreads();

    // ---- PV + gate epilogue ----
    const int d0 = (tid & 15) * 2;
    float acc0 = 0.0f, acc1 = 0.0f;
    for (int kc = 0; kc < 8; kc++) {
        __syncthreads();
#pragma unroll
        for (int i = 0; i < 2; i++) {
            int v  = i * 256 + tid;
            int r  = v >> 3;
            int d4 = (v & 7) * 4;
            *(float4*)&cs[r][d4] =
                *(const float4*)(vbase + (size_t)(kc * 64 + r) * C_ + d4);
        }
        __syncthreads();
#pragma unroll
        for (int kk = 0; kk < 64; kk++) {
            float w   = ss[qi][kc * 64 + kk];
            float2 vv = *(const float2*)&cs[kk][d0];
            acc0 += w * vv.x;
            acc1 += w * vv.y;
        }
    }

    const size_t oidx = ((size_t)(b * Q_ + q0 + qi) * C_ + h * HD_ + d0);
    g_wa[oidx]     = acc0 * g_gate[oidx];
    g_wa[oidx + 1] = acc1 * g_gate[oidx + 1];
}

// ---------------- launch ------------------------------------------------------
extern "C" void kernel_launch(void* const* d_in, const int* in_sizes, int n_in,
                              void* d_out, int out_size) {
    const float* q_data    = (const float*)d_in[0];
    const float* m_data    = (const float*)d_in[1];
    const float* bias      = (const float*)d_in[2];
    const float* nbb       = (const float*)d_in[3];
    const float* query_w   = (const float*)d_in[4];
    const float* key_w     = (const float*)d_in[5];
    const float* value_w   = (const float*)d_in[6];
    const float* gating_w  = (const float*)d_in[7];
    const float* gating_b  = (const float*)d_in[8];
    const float* output_w  = (const float*)d_in[9];
    const float* output_b  = (const float*)d_in[10];
    float* out = (float*)d_out;

    // q + gate projections  [32768,256] x [256,512]
    proj_kernel<0><<<dim3(512, 8), 256>>>(q_data, query_w, gating_w, gating_b, nullptr);
    // k + v projections
    proj_kernel<1><<<dim3(512, 8), 256>>>(m_data, key_w, value_w, nullptr, nullptr);
    // fused attention + gating
    attn_kernel<<<dim3(Q_ / 16, H_, B_), 256>>>(bias, nbb);
    // output projection + bias
    proj_kernel<2><<<dim3(512, 4), 256>>>(nullptr, output_w, nullptr, output_b, out);
}

// round 4
// speedup vs baseline: 4.2136x; 4.2136x over previous
#include <cuda_runtime.h>
#include <math.h>
#include <stdint.h>

#define B_   64
#define Q_   512
#define KK_  512
#define C_   256
#define H_   8
#define HD_  32
#define OUT_ 256
#define SCALE_Q 0.17677669529663687f   // 1/sqrt(32)

// ---------------- scratch (static device globals; no allocation) -------------
__device__ float g_q[B_ * Q_ * C_];      // scaled q projection  [b,q,h*32+d]
__device__ float g_gate[B_ * Q_ * C_];   // sigmoid gate         [b,q,h*32+d]
__device__ float g_k[B_ * KK_ * C_];     // k projection         [b,k,h*32+d]
__device__ float g_v[B_ * KK_ * C_];     // v projection         [b,k,h*32+d]
__device__ float g_wa[B_ * Q_ * C_];     // gated weighted avg   [b,q,h*32+d]

// ---------------- tf32 helpers ------------------------------------------------
__device__ __forceinline__ uint32_t f2tf(float x) {
    uint32_t u;
    asm("cvt.rna.tf32.f32 %0, %1;" : "=r"(u) : "f"(x));
    return u;
}
__device__ __forceinline__ void cvt4(uint32_t* d, float4 v) {
    d[0] = f2tf(v.x); d[1] = f2tf(v.y); d[2] = f2tf(v.z); d[3] = f2tf(v.w);
}
// D += A(16x8) * B(8x8), tf32 in, f32 acc
__device__ __forceinline__ void mma8(float* d, const uint32_t* a, const uint32_t* b) {
    asm volatile(
        "mma.sync.aligned.m16n8k8.row.col.f32.tf32.tf32.f32 "
        "{%0,%1,%2,%3}, {%4,%5,%6,%7}, {%8,%9}, {%0,%1,%2,%3};"
        : "+f"(d[0]), "+f"(d[1]), "+f"(d[2]), "+f"(d[3])
        : "r"(a[0]), "r"(a[1]), "r"(a[2]), "r"(a[3]), "r"(b[0]), "r"(b[1]));
}

// ---------------- tf32 projection GEMM ---------------------------------------
// C[M,*] = A[M,256] x W[256,256(+256)], BM=128, BN=64, BK=32, 256 thr, 8 warps
// warp grid 4(m) x 2(n): warp tile 32x32 = 2 mfrag x 4 nfrag (m16n8k8)
// MODE 0: A=q_data -> g_q*SCALE (bn<4) / sigmoid gate (bn>=4, W1,gating_b)
// MODE 1: A=m_data -> g_k / g_v
// MODE 2: A=g_wa   -> Dout + output_b
#define LDA 36
#define LDB 72
template <int MODE>
__global__ void __launch_bounds__(256) proj_tc(const float* __restrict__ A,
                                               const float* __restrict__ W0,
                                               const float* __restrict__ W1,
                                               const float* __restrict__ bvec,
                                               float* __restrict__ Dout) {
    __shared__ uint32_t As[128 * LDA];   // 18 KB
    __shared__ uint32_t Bs[32 * LDB];    // 9 KB

    const int tid  = threadIdx.x;
    const int m0   = blockIdx.x * 128;
    const int bn   = blockIdx.y;
    const int warp = tid >> 5, lane = tid & 31;
    const int g = lane >> 2, t = lane & 3;
    const int wm = warp >> 1, wn = warp & 1;

    const float* Ap = (MODE == 2) ? g_wa : A;
    const float* W  = (MODE == 2) ? W0 : (bn < 4 ? W0 : W1);
    const int ncol  = (MODE == 2) ? bn * 64 : (bn & 3) * 64;

    float acc[2][4][4];
#pragma unroll
    for (int i = 0; i < 2; i++)
#pragma unroll
        for (int j = 0; j < 4; j++)
#pragma unroll
            for (int c = 0; c < 4; c++) acc[i][j][c] = 0.0f;

    for (int k0 = 0; k0 < 256; k0 += 32) {
        // A tile 128x32 -> 1024 float4, 4/thread
#pragma unroll
        for (int i = 0; i < 4; i++) {
            int v = i * 256 + tid;
            int r = v >> 3, c4 = (v & 7) * 4;
            float4 a4 = *(const float4*)(Ap + (size_t)(m0 + r) * 256 + k0 + c4);
            uint32_t u[4]; cvt4(u, a4);
            *(uint4*)&As[r * LDA + c4] = *(uint4*)u;
        }
        // W tile 32x64 -> 512 float4, 2/thread
#pragma unroll
        for (int i = 0; i < 2; i++) {
            int v = i * 256 + tid;
            int r = v >> 4, c4 = (v & 15) * 4;
            float4 b4 = *(const float4*)(W + (size_t)(k0 + r) * 256 + ncol + c4);
            uint32_t u[4]; cvt4(u, b4);
            *(uint4*)&Bs[r * LDB + c4] = *(uint4*)u;
        }
        __syncthreads();

#pragma unroll
        for (int kk = 0; kk < 4; kk++) {
            const int k8 = kk * 8;
            uint32_t af[2][4], bf[4][2];
#pragma unroll
            for (int i = 0; i < 2; i++) {
                const int rb = wm * 32 + i * 16;
                af[i][0] = As[(rb + g) * LDA + k8 + t];
                af[i][1] = As[(rb + g + 8) * LDA + k8 + t];
                af[i][2] = As[(rb + g) * LDA + k8 + t + 4];
                af[i][3] = As[(rb + g + 8) * LDA + k8 + t + 4];
            }
#pragma unroll
            for (int j = 0; j < 4; j++) {
                const int nb = wn * 32 + j * 8;
                bf[j][0] = Bs[(k8 + t) * LDB + nb + g];
                bf[j][1] = Bs[(k8 + t + 4) * LDB + nb + g];
            }
#pragma unroll
            for (int i = 0; i < 2; i++)
#pragma unroll
                for (int j = 0; j < 4; j++) mma8(acc[i][j], af[i], bf[j]);
        }
        __syncthreads();
    }

    // epilogue
#pragma unroll
    for (int i = 0; i < 2; i++) {
        const int r0 = m0 + wm * 32 + i * 16 + g;
#pragma unroll
        for (int j = 0; j < 4; j++) {
            const int cb = ncol + wn * 32 + j * 8 + 2 * t;  // even col
            const float* c = acc[i][j];
#pragma unroll
            for (int half = 0; half < 2; half++) {
                const int row = r0 + half * 8;
                float v0 = c[half * 2 + 0], v1 = c[half * 2 + 1];
                if (MODE == 0) {
                    if (bn < 4) {
                        *(float2*)&g_q[(size_t)row * 256 + cb] =
                            make_float2(v0 * SCALE_Q, v1 * SCALE_Q);
                    } else {
                        float s0 = 1.0f / (1.0f + __expf(-(v0 + bvec[cb])));
                        float s1 = 1.0f / (1.0f + __expf(-(v1 + bvec[cb + 1])));
                        *(float2*)&g_gate[(size_t)row * 256 + cb] = make_float2(s0, s1);
                    }
                } else if (MODE == 1) {
                    float* dst = (bn < 4) ? g_k : g_v;
                    *(float2*)&dst[(size_t)row * 256 + cb] = make_float2(v0, v1);
                } else {
                    *(float2*)&Dout[(size_t)row * 256 + cb] =
                        make_float2(v0 + bvec[cb], v1 + bvec[cb + 1]);
                }
            }
        }
    }
}

// ---------------- tensor-core attention --------------------------------------
// grid (Q/32, H, B), 256 thr (8 warps). Dynamic smem:
//   qs : 32 x 36 tf32
//   S  : 32 x 516 f32 (logits -> weights)
//   kv : 128 x 40 tf32 (K chunk LD=36, V chunk LD=40)
#define LDQ  36
#define LDSS 516
#define LDK  36
#define LDV  40
#define QS_W   (32 * LDQ)
#define S_W    (32 * LDSS)
#define KV_W   (128 * LDV)
#define ATTN_SMEM_BYTES ((QS_W + S_W + KV_W) * 4)

__global__ void __launch_bounds__(256) attn_tc(const float* __restrict__ bias,
                                               const float* __restrict__ nbb) {
    extern __shared__ uint32_t smem[];
    uint32_t* qs = smem;
    float*    S  = (float*)(smem + QS_W);
    uint32_t* kv = smem + QS_W + S_W;

    const int tid = threadIdx.x;
    const int q0  = blockIdx.x * 32;
    const int h   = blockIdx.y;
    const int b   = blockIdx.z;
    const int warp = tid >> 5, lane = tid & 31;
    const int g = lane >> 2, t = lane & 3;
    const int mh = warp >> 2;          // 0/1: q-row half
    const int nq = warp & 3;           // quarter for S cols / d-frag for PV

    const float* qbase = g_q + ((size_t)(b * Q_ + q0) * C_ + h * HD_);
    const float* kbase = g_k + ((size_t)b * KK_ * C_ + h * HD_);
    const float* vbase = g_v + ((size_t)b * KK_ * C_ + h * HD_);

    // load q tile 32x32 (256 float4, 1/thread)
    {
        int r = tid >> 3, c4 = (tid & 7) * 4;
        float4 a4 = *(const float4*)(qbase + (size_t)r * C_ + c4);
        uint32_t u[4]; cvt4(u, a4);
        *(uint4*)&qs[r * LDQ + c4] = *(uint4*)u;
    }

    // ---- S = q k^T (+ bias + nbb), chunks of 128 keys ----
    for (int kc = 0; kc < 4; kc++) {
        __syncthreads();  // prev chunk's mma reads done / q load visible
        // load K chunk 128x32 (1024 float4, 4/thread), LD=36
#pragma unroll
        for (int i = 0; i < 4; i++) {
            int v = i * 256 + tid;
            int r = v >> 3, c4 = (v & 7) * 4;
            float4 a4 = *(const float4*)(kbase + (size_t)(kc * 128 + r) * C_ + c4);
            uint32_t u[4]; cvt4(u, a4);
            *(uint4*)&kv[r * LDK + c4] = *(uint4*)u;
        }
        __syncthreads();

        float acc[4][4];
#pragma unroll
        for (int j = 0; j < 4; j++)
#pragma unroll
            for (int c = 0; c < 4; c++) acc[j][c] = 0.0f;

#pragma unroll
        for (int kk = 0; kk < 4; kk++) {   // HD=32 -> 4 k-steps
            const int k8 = kk * 8;
            uint32_t af[4];
            const int rb = mh * 16;
            af[0] = qs[(rb + g) * LDQ + k8 + t];
            af[1] = qs[(rb + g + 8) * LDQ + k8 + t];
            af[2] = qs[(rb + g) * LDQ + k8 + t + 4];
            af[3] = qs[(rb + g + 8) * LDQ + k8 + t + 4];
#pragma unroll
            for (int j = 0; j < 4; j++) {
                const int nb = nq * 32 + j * 8;   // key within chunk
                uint32_t bf[2];
                bf[0] = kv[(nb + g) * LDK + k8 + t];
                bf[1] = kv[(nb + g) * LDK + k8 + t + 4];
                mma8(acc[j], af, bf);
            }
        }

        // store S chunk with biases (cols 2t,2t+1 contiguous)
#pragma unroll
        for (int j = 0; j < 4; j++) {
            const int colc = kc * 128 + nq * 32 + j * 8 + 2 * t;
#pragma unroll
            for (int half = 0; half < 2; half++) {
                const int row = mh * 16 + g + half * 8;
                float2 bi = *(const float2*)(bias +
                    ((size_t)(b * Q_ + q0 + row)) * KK_ + colc);
                float2 ni = *(const float2*)(nbb +
                    ((size_t)(h * Q_ + q0 + row)) * KK_ + colc);
                S[row * LDSS + colc]     = acc[j][half * 2 + 0] + bi.x + ni.x;
                S[row * LDSS + colc + 1] = acc[j][half * 2 + 1] + bi.y + ni.y;
            }
        }
    }
    __syncthreads();

    // ---- softmax, 4 rows per warp ----
#pragma unroll
    for (int rr = 0; rr < 4; rr++) {
        const int r = warp * 4 + rr;
        float* row = S + r * LDSS;
        float mx = -1e30f;
#pragma unroll
        for (int k = lane; k < 512; k += 32) mx = fmaxf(mx, row[k]);
#pragma unroll
        for (int o = 16; o > 0; o >>= 1)
            mx = fmaxf(mx, __shfl_xor_sync(0xffffffff, mx, o));
        float sum = 0.0f;
#pragma unroll
        for (int k = lane; k < 512; k += 32) {
            float e = __expf(row[k] - mx);
            row[k] = e;
            sum += e;
        }
#pragma unroll
        for (int o = 16; o > 0; o >>= 1)
            sum += __shfl_xor_sync(0xffffffff, sum, o);
        const float inv = 1.0f / sum;
#pragma unroll
        for (int k = lane; k < 512; k += 32) row[k] *= inv;
    }

    // ---- PV: out[32x32] = W[32x512] * V[512x32] ----
    float pv[4] = {0.0f, 0.0f, 0.0f, 0.0f};
    const int dn = nq * 8;   // d columns for this warp
    for (int kc = 0; kc < 4; kc++) {
        __syncthreads();  // softmax done / prev chunk consumed
        // load V chunk 128x32, LD=40
#pragma unroll
        for (int i = 0; i < 4; i++) {
            int v = i * 256 + tid;
            int r = v >> 3, c4 = (v & 7) * 4;
            float4 a4 = *(const float4*)(vbase + (size_t)(kc * 128 + r) * C_ + c4);
            uint32_t u[4]; cvt4(u, a4);
            *(uint4*)&kv[r * LDV + c4] = *(uint4*)u;
        }
        __syncthreads();

#pragma unroll
        for (int ks = 0; ks < 16; ks++) {   // 128 keys / 8
            const int k8 = ks * 8;
            uint32_t af[4];
            const int rb = mh * 16;
            const int ck = kc * 128 + k8;
            af[0] = f2tf(S[(rb + g) * LDSS + ck + t]);
            af[1] = f2tf(S[(rb + g + 8) * LDSS + ck + t]);
            af[2] = f2tf(S[(rb + g) * LDSS + ck + t + 4]);
            af[3] = f2tf(S[(rb + g + 8) * LDSS + ck + t + 4]);
            uint32_t bf[2];
            bf[0] = kv[(k8 + t) * LDV + dn + g];
            bf[1] = kv[(k8 + t + 4) * LDV + dn + g];
            mma8(pv, af, bf);
        }
    }

    // ---- gate + store ----
#pragma unroll
    for (int half = 0; half < 2; half++) {
        const int row = mh * 16 + g + half * 8;
        const int d   = dn + 2 * t;
        const size_t oidx = ((size_t)(b * Q_ + q0 + row)) * C_ + h * HD_ + d;
        float2 ga = *(const float2*)&g_gate[oidx];
        *(float2*)&g_wa[oidx] =
            make_float2(pv[half * 2 + 0] * ga.x, pv[half * 2 + 1] * ga.y);
    }
}

// ---------------- launch ------------------------------------------------------
extern "C" void kernel_launch(void* const* d_in, const int* in_sizes, int n_in,
                              void* d_out, int out_size) {
    const float* q_data    = (const float*)d_in[0];
    const float* m_data    = (const float*)d_in[1];
    const float* bias      = (const float*)d_in[2];
    const float* nbb       = (const float*)d_in[3];
    const float* query_w   = (const float*)d_in[4];
    const float* key_w     = (const float*)d_in[5];
    const float* value_w   = (const float*)d_in[6];
    const float* gating_w  = (const float*)d_in[7];
    const float* gating_b  = (const float*)d_in[8];
    const float* output_w  = (const float*)d_in[9];
    const float* output_b  = (const float*)d_in[10];
    float* out = (float*)d_out;

    cudaFuncSetAttribute(attn_tc, cudaFuncAttributeMaxDynamicSharedMemorySize,
                         ATTN_SMEM_BYTES);

    // q + gate projections  [32768,256] x [256,512]
    proj_tc<0><<<dim3(256, 8), 256>>>(q_data, query_w, gating_w, gating_b, nullptr);
    // k + v projections
    proj_tc<1><<<dim3(256, 8), 256>>>(m_data, key_w, value_w, nullptr, nullptr);
    // tensor-core attention + gating
    attn_tc<<<dim3(Q_ / 32, H_, B_), 256, ATTN_SMEM_BYTES>>>(bias, nbb);
    // output projection + bias
    proj_tc<2><<<dim3(256, 4), 256>>>(nullptr, output_w, nullptr, output_b, out);
}

// round 5
// speedup vs baseline: 5.4044x; 1.2826x over previous
#include <cuda_runtime.h>
#include <math.h>
#include <stdint.h>

#define B_   64
#define Q_   512
#define KK_  512
#define C_   256
#define H_   8
#define HD_  32
#define OUT_ 256
#define SCALE_Q 0.17677669529663687f   // 1/sqrt(32)

// ---------------- scratch (static device globals; no allocation) -------------
__device__ __align__(16) float g_q[B_ * Q_ * C_];     // tf32-rounded scaled q
__device__ __align__(16) float g_gate[B_ * Q_ * C_];  // sigmoid gate (fp32)
__device__ __align__(16) float g_k[B_ * KK_ * C_];    // tf32-rounded k
__device__ __align__(16) float g_v[B_ * KK_ * C_];    // tf32-rounded v
__device__ __align__(16) float g_wa[B_ * Q_ * C_];    // gated weighted avg (fp32)

// ---------------- tf32 / mma / cp.async helpers -------------------------------
__device__ __forceinline__ uint32_t f2tf(float x) {
    uint32_t u;
    asm("cvt.rna.tf32.f32 %0, %1;" : "=r"(u) : "f"(x));
    return u;
}
__device__ __forceinline__ void cvt4(uint32_t* d, float4 v) {
    d[0] = f2tf(v.x); d[1] = f2tf(v.y); d[2] = f2tf(v.z); d[3] = f2tf(v.w);
}
__device__ __forceinline__ void mma8(float* d, const uint32_t* a, const uint32_t* b) {
    asm volatile(
        "mma.sync.aligned.m16n8k8.row.col.f32.tf32.tf32.f32 "
        "{%0,%1,%2,%3}, {%4,%5,%6,%7}, {%8,%9}, {%0,%1,%2,%3};"
        : "+f"(d[0]), "+f"(d[1]), "+f"(d[2]), "+f"(d[3])
        : "r"(a[0]), "r"(a[1]), "r"(a[2]), "r"(a[3]), "r"(b[0]), "r"(b[1]));
}
__device__ __forceinline__ void cp16(uint32_t dst, const float* src) {
    asm volatile("cp.async.ca.shared.global [%0], [%1], 16;" :: "r"(dst), "l"(src));
}
#define CP_COMMIT() asm volatile("cp.async.commit_group;")
#define CP_WAIT1()  asm volatile("cp.async.wait_group 1;")

// ---------------- tf32 projection GEMM (as R4, + tf32-rounded outputs) -------
#define LDA 36
#define LDB 72
template <int MODE>
__global__ void __launch_bounds__(256) proj_tc(const float* __restrict__ A,
                                               const float* __restrict__ W0,
                                               const float* __restrict__ W1,
                                               const float* __restrict__ bvec,
                                               float* __restrict__ Dout) {
    __shared__ uint32_t As[128 * LDA];
    __shared__ uint32_t Bs[32 * LDB];

    const int tid  = threadIdx.x;
    const int m0   = blockIdx.x * 128;
    const int bn   = blockIdx.y;
    const int warp = tid >> 5, lane = tid & 31;
    const int g = lane >> 2, t = lane & 3;
    const int wm = warp >> 1, wn = warp & 1;

    const float* Ap = (MODE == 2) ? g_wa : A;
    const float* W  = (MODE == 2) ? W0 : (bn < 4 ? W0 : W1);
    const int ncol  = (MODE == 2) ? bn * 64 : (bn & 3) * 64;

    float acc[2][4][4];
#pragma unroll
    for (int i = 0; i < 2; i++)
#pragma unroll
        for (int j = 0; j < 4; j++)
#pragma unroll
            for (int c = 0; c < 4; c++) acc[i][j][c] = 0.0f;

    for (int k0 = 0; k0 < 256; k0 += 32) {
#pragma unroll
        for (int i = 0; i < 4; i++) {
            int v = i * 256 + tid;
            int r = v >> 3, c4 = (v & 7) * 4;
            float4 a4 = *(const float4*)(Ap + (size_t)(m0 + r) * 256 + k0 + c4);
            uint32_t u[4]; cvt4(u, a4);
            *(uint4*)&As[r * LDA + c4] = *(uint4*)u;
        }
#pragma unroll
        for (int i = 0; i < 2; i++) {
            int v = i * 256 + tid;
            int r = v >> 4, c4 = (v & 15) * 4;
            float4 b4 = *(const float4*)(W + (size_t)(k0 + r) * 256 + ncol + c4);
            uint32_t u[4]; cvt4(u, b4);
            *(uint4*)&Bs[r * LDB + c4] = *(uint4*)u;
        }
        __syncthreads();

#pragma unroll
        for (int kk = 0; kk < 4; kk++) {
            const int k8 = kk * 8;
            uint32_t af[2][4], bf[4][2];
#pragma unroll
            for (int i = 0; i < 2; i++) {
                const int rb = wm * 32 + i * 16;
                af[i][0] = As[(rb + g) * LDA + k8 + t];
                af[i][1] = As[(rb + g + 8) * LDA + k8 + t];
                af[i][2] = As[(rb + g) * LDA + k8 + t + 4];
                af[i][3] = As[(rb + g + 8) * LDA + k8 + t + 4];
            }
#pragma unroll
            for (int j = 0; j < 4; j++) {
                const int nb = wn * 32 + j * 8;
                bf[j][0] = Bs[(k8 + t) * LDB + nb + g];
                bf[j][1] = Bs[(k8 + t + 4) * LDB + nb + g];
            }
#pragma unroll
            for (int i = 0; i < 2; i++)
#pragma unroll
                for (int j = 0; j < 4; j++) mma8(acc[i][j], af[i], bf[j]);
        }
        __syncthreads();
    }

#pragma unroll
    for (int i = 0; i < 2; i++) {
        const int r0 = m0 + wm * 32 + i * 16 + g;
#pragma unroll
        for (int j = 0; j < 4; j++) {
            const int cb = ncol + wn * 32 + j * 8 + 2 * t;
            const float* c = acc[i][j];
#pragma unroll
            for (int half = 0; half < 2; half++) {
                const int row = r0 + half * 8;
                float v0 = c[half * 2 + 0], v1 = c[half * 2 + 1];
                if (MODE == 0) {
                    if (bn < 4) {
                        *(float2*)&g_q[(size_t)row * 256 + cb] = make_float2(
                            __uint_as_float(f2tf(v0 * SCALE_Q)),
                            __uint_as_float(f2tf(v1 * SCALE_Q)));
                    } else {
                        float s0 = 1.0f / (1.0f + __expf(-(v0 + bvec[cb])));
                        float s1 = 1.0f / (1.0f + __expf(-(v1 + bvec[cb + 1])));
                        *(float2*)&g_gate[(size_t)row * 256 + cb] = make_float2(s0, s1);
                    }
                } else if (MODE == 1) {
                    float* dst = (bn < 4) ? g_k : g_v;
                    *(float2*)&dst[(size_t)row * 256 + cb] = make_float2(
                        __uint_as_float(f2tf(v0)), __uint_as_float(f2tf(v1)));
                } else {
                    *(float2*)&Dout[(size_t)row * 256 + cb] =
                        make_float2(v0 + bvec[cb], v1 + bvec[cb + 1]);
                }
            }
        }
    }
}

// ---------------- flash attention, register-resident P -----------------------
// grid (Q/64, H, B), 256 thr (8 warps). Warp (wm 0..3: 16 q-rows, wn 0..1: key half).
// K chunks of 64 keys, online softmax, P->PV via intra-quad shuffles.
#define ALD 36
#define OFF_Q    0
#define OFF_K    (OFF_Q + 64 * ALD)
#define OFF_V    (OFF_K + 2 * 64 * ALD)
#define OFF_MAX  (OFF_V + 2 * 64 * ALD)
#define OFF_SUMB (OFF_MAX + 128)
#define OFF_O    (OFF_SUMB + 64)
#define ATTN_WORDS (OFF_O + 64 * 32)
#define ATTN_BYTES (ATTN_WORDS * 4)

__device__ __forceinline__ void issue_kv(uint32_t smem_u32, const float* kbase,
                                         const float* vbase, int kc, int tid) {
    const int st = kc & 1;
#pragma unroll
    for (int i = 0; i < 2; i++) {
        int v = i * 256 + tid;
        int r = v >> 3, c4 = (v & 7) * 4;
        const size_t goff = (size_t)(kc * 64 + r) * C_ + c4;
        cp16(smem_u32 + (OFF_K + st * 64 * ALD + r * ALD + c4) * 4, kbase + goff);
        cp16(smem_u32 + (OFF_V + st * 64 * ALD + r * ALD + c4) * 4, vbase + goff);
    }
}

__global__ void __launch_bounds__(256) attn_flash(const float* __restrict__ bias,
                                                  const float* __restrict__ nbb) {
    extern __shared__ uint32_t sm[];
    uint32_t* qsm  = sm + OFF_Q;
    float*    smax = (float*)(sm + OFF_MAX);
    float*    ssumB = (float*)(sm + OFF_SUMB);
    float*    Obuf = (float*)(sm + OFF_O);

    const int tid = threadIdx.x;
    const int q0  = blockIdx.x * 64;
    const int h   = blockIdx.y;
    const int b   = blockIdx.z;
    const int warp = tid >> 5, lane = tid & 31;
    const int g = lane >> 2, t = lane & 3;
    const int wm = warp >> 1, wn = warp & 1;

    const float* qbase = g_q + ((size_t)(b * Q_ + q0)) * C_ + h * HD_;
    const float* kbase = g_k + ((size_t)b * KK_) * C_ + h * HD_;
    const float* vbase = g_v + ((size_t)b * KK_) * C_ + h * HD_;
    const uint32_t smem_u32 = (uint32_t)__cvta_generic_to_shared(sm);

    // load q tile 64x32 (pre-rounded tf32; 2 float4/thread)
#pragma unroll
    for (int i = 0; i < 2; i++) {
        int v = i * 256 + tid;
        int r = v >> 3, c4 = (v & 7) * 4;
        *(float4*)&qsm[r * ALD + c4] = *(const float4*)(qbase + (size_t)r * C_ + c4);
    }
    // prefetch chunks 0,1
    issue_kv(smem_u32, kbase, vbase, 0, tid); CP_COMMIT();
    issue_kv(smem_u32, kbase, vbase, 1, tid); CP_COMMIT();
    __syncthreads();

    // q fragments -> registers
    uint32_t af[4][4];
#pragma unroll
    for (int k = 0; k < 4; k++) {
        af[k][0] = qsm[(wm * 16 + g) * ALD + k * 8 + t];
        af[k][1] = qsm[(wm * 16 + g + 8) * ALD + k * 8 + t];
        af[k][2] = qsm[(wm * 16 + g) * ALD + k * 8 + t + 4];
        af[k][3] = qsm[(wm * 16 + g + 8) * ALD + k * 8 + t + 4];
    }

    const int r0 = wm * 16 + g, r1 = r0 + 8;
    const float* brow0 = bias + ((size_t)(b * Q_ + q0 + r0)) * KK_;
    const float* brow1 = bias + ((size_t)(b * Q_ + q0 + r1)) * KK_;
    const float* nrow0 = nbb + ((size_t)(h * Q_ + q0 + r0)) * KK_;
    const float* nrow1 = nbb + ((size_t)(h * Q_ + q0 + r1)) * KK_;

    float rm0 = -1e30f, rm1 = -1e30f;   // running max (rows r0, r1)
    float rs0 = 0.0f, rs1 = 0.0f;       // running sum (this key-half)
    float o[4][4];
#pragma unroll
    for (int nf = 0; nf < 4; nf++)
#pragma unroll
        for (int c = 0; c < 4; c++) o[nf][c] = 0.0f;

    for (int kc = 0; kc < 8; kc++) {
        const int st = kc & 1;
        const uint32_t* Kb = sm + OFF_K + st * 64 * ALD;
        const uint32_t* Vb = sm + OFF_V + st * 64 * ALD;
        CP_WAIT1();
        __syncthreads();

        // ---- S = q k^T for this warp's 16x32 slab ----
        float s[4][4];
#pragma unroll
        for (int j = 0; j < 4; j++)
#pragma unroll
            for (int c = 0; c < 4; c++) s[j][c] = 0.0f;
#pragma unroll
        for (int k = 0; k < 4; k++) {
            const int k8 = k * 8;
#pragma unroll
            for (int j = 0; j < 4; j++) {
                const int nb = wn * 32 + j * 8;
                uint32_t bf[2];
                bf[0] = Kb[(nb + g) * ALD + k8 + t];
                bf[1] = Kb[(nb + g) * ALD + k8 + t + 4];
                mma8(s[j], af[k], bf);
            }
        }

        // ---- bias + nbb, per-thread row max ----
        float m0v = -1e30f, m1v = -1e30f;
#pragma unroll
        for (int j = 0; j < 4; j++) {
            const int col = kc * 64 + wn * 32 + j * 8 + 2 * t;
            float2 b0 = *(const float2*)(brow0 + col);
            float2 n0 = *(const float2*)(nrow0 + col);
            float2 b1 = *(const float2*)(brow1 + col);
            float2 n1 = *(const float2*)(nrow1 + col);
            s[j][0] += b0.x + n0.x; s[j][1] += b0.y + n0.y;
            s[j][2] += b1.x + n1.x; s[j][3] += b1.y + n1.y;
            m0v = fmaxf(m0v, fmaxf(s[j][0], s[j][1]));
            m1v = fmaxf(m1v, fmaxf(s[j][2], s[j][3]));
        }
        m0v = fmaxf(m0v, __shfl_xor_sync(0xffffffff, m0v, 1));
        m0v = fmaxf(m0v, __shfl_xor_sync(0xffffffff, m0v, 2));
        m1v = fmaxf(m1v, __shfl_xor_sync(0xffffffff, m1v, 1));
        m1v = fmaxf(m1v, __shfl_xor_sync(0xffffffff, m1v, 2));
        smax[wn * 64 + r0] = m0v;
        smax[wn * 64 + r1] = m1v;
        __syncthreads();
        const float cm0 = fmaxf(smax[r0], smax[64 + r0]);
        const float cm1 = fmaxf(smax[r1], smax[64 + r1]);
        const float nm0 = fmaxf(rm0, cm0), nm1 = fmaxf(rm1, cm1);
        const float c0 = __expf(rm0 - nm0), c1 = __expf(rm1 - nm1);
        rm0 = nm0; rm1 = nm1;

        // ---- exp + partial sums ----
        float sum0 = 0.0f, sum1 = 0.0f;
#pragma unroll
        for (int j = 0; j < 4; j++) {
            s[j][0] = __expf(s[j][0] - nm0); s[j][1] = __expf(s[j][1] - nm0);
            s[j][2] = __expf(s[j][2] - nm1); s[j][3] = __expf(s[j][3] - nm1);
            sum0 += s[j][0] + s[j][1];
            sum1 += s[j][2] + s[j][3];
        }
        sum0 += __shfl_xor_sync(0xffffffff, sum0, 1);
        sum0 += __shfl_xor_sync(0xffffffff, sum0, 2);
        sum1 += __shfl_xor_sync(0xffffffff, sum1, 1);
        sum1 += __shfl_xor_sync(0xffffffff, sum1, 2);
        rs0 = rs0 * c0 + sum0;
        rs1 = rs1 * c1 + sum1;

        // ---- rescale O ----
#pragma unroll
        for (int nf = 0; nf < 4; nf++) {
            o[nf][0] *= c0; o[nf][1] *= c0;
            o[nf][2] *= c1; o[nf][3] *= c1;
        }

        // ---- PV: rearrange P (C-frag) -> A-frag via quad shuffles ----
#pragma unroll
        for (int j = 0; j < 4; j++) {
            const int srcA = (lane & ~3) | (t >> 1);
            const int srcB = (lane & ~3) | 2 | (t >> 1);
            float v00 = __shfl_sync(0xffffffff, s[j][0], srcA);
            float v01 = __shfl_sync(0xffffffff, s[j][1], srcA);
            float v20 = __shfl_sync(0xffffffff, s[j][2], srcA);
            float v21 = __shfl_sync(0xffffffff, s[j][3], srcA);
            float w00 = __shfl_sync(0xffffffff, s[j][0], srcB);
            float w01 = __shfl_sync(0xffffffff, s[j][1], srcB);
            float w20 = __shfl_sync(0xffffffff, s[j][2], srcB);
            float w21 = __shfl_sync(0xffffffff, s[j][3], srcB);
            uint32_t pa[4];
            pa[0] = f2tf((t & 1) ? v01 : v00);   // P[r0][j8+t]
            pa[1] = f2tf((t & 1) ? v21 : v20);   // P[r1][j8+t]
            pa[2] = f2tf((t & 1) ? w01 : w00);   // P[r0][j8+t+4]
            pa[3] = f2tf((t & 1) ? w21 : w20);   // P[r1][j8+t+4]
            const int krow = wn * 32 + j * 8;
#pragma unroll
            for (int nf = 0; nf < 4; nf++) {
                uint32_t bf[2];
                bf[0] = Vb[(krow + t) * ALD + nf * 8 + g];
                bf[1] = Vb[(krow + t + 4) * ALD + nf * 8 + g];
                mma8(o[nf], pa, bf);
            }
        }
        __syncthreads();
        if (kc + 2 < 8) issue_kv(smem_u32, kbase, vbase, kc + 2, tid);
        CP_COMMIT();
    }

    // ---- combine key-halves, normalize, gate, store ----
    if (wn == 1) {
#pragma unroll
        for (int half = 0; half < 2; half++) {
            const int r = half ? r1 : r0;
            ssumB[r] = half ? rs1 : rs0;
#pragma unroll
            for (int nf = 0; nf < 4; nf++)
                *(float2*)&Obuf[r * 32 + nf * 8 + 2 * t] =
                    make_float2(o[nf][half * 2], o[nf][half * 2 + 1]);
        }
    }
    __syncthreads();
    if (wn == 0) {
#pragma unroll
        for (int half = 0; half < 2; half++) {
            const int r = half ? r1 : r0;
            const float inv = 1.0f / ((half ? rs1 : rs0) + ssumB[r]);
            const size_t obase = ((size_t)(b * Q_ + q0 + r)) * C_ + h * HD_;
#pragma unroll
            for (int nf = 0; nf < 4; nf++) {
                const int d = nf * 8 + 2 * t;
                float2 part = *(float2*)&Obuf[r * 32 + d];
                float2 ga = *(const float2*)&g_gate[obase + d];
                *(float2*)&g_wa[obase + d] = make_float2(
                    (o[nf][half * 2] + part.x) * inv * ga.x,
                    (o[nf][half * 2 + 1] + part.y) * inv * ga.y);
            }
        }
    }
}

// ---------------- launch ------------------------------------------------------
extern "C" void kernel_launch(void* const* d_in, const int* in_sizes, int n_in,
                              void* d_out, int out_size) {
    const float* q_data    = (const float*)d_in[0];
    const float* m_data    = (const float*)d_in[1];
    const float* bias      = (const float*)d_in[2];
    const float* nbb       = (const float*)d_in[3];
    const float* query_w   = (const float*)d_in[4];
    const float* key_w     = (const float*)d_in[5];
    const float* value_w   = (const float*)d_in[6];
    const float* gating_w  = (const float*)d_in[7];
    const float* gating_b  = (const float*)d_in[8];
    const float* output_w  = (const float*)d_in[9];
    const float* output_b  = (const float*)d_in[10];
    float* out = (float*)d_out;

    cudaFuncSetAttribute(attn_flash, cudaFuncAttributeMaxDynamicSharedMemorySize,
                         ATTN_BYTES);

    proj_tc<0><<<dim3(256, 8), 256>>>(q_data, query_w, gating_w, gating_b, nullptr);
    proj_tc<1><<<dim3(256, 8), 256>>>(m_data, key_w, value_w, nullptr, nullptr);
    attn_flash<<<dim3(Q_ / 64, H_, B_), 256, ATTN_BYTES>>>(bias, nbb);
    proj_tc<2><<<dim3(256, 4), 256>>>(nullptr, output_w, nullptr, output_b, out);
}